// round 8
// baseline (speedup 1.0000x reference)
#include <cuda_runtime.h>
#include <cstdint>

// ===========================================================================
// TemporalAttention — tf32 mma.sync GEMMs (tcgen05 unavailable: toolchain
// targets sm_103 without the 'a' feature set) + fused attention.
//
//   s = b*1024 + hh*32 + ww   (spatial index, 2048 total)
//   x[b][c][f][hh][ww] flat = b*8388608 + c*16384 + f*1024 + s_local
//   g_qkv[(f*2048 + s)][n]  n in [0,1536): q|k|v each 512  (f-major rows)
//   g_att[(f*2048 + s)][j]  j in [0,512)
//
// GEMM CTA tile 128(M) x 256(N), 8 warps in 2x4 grid, warp tile 64x64.
// Fragment-smem bytes/MAC is the measured bound; 64x64 warp tiles cut it 33%
// vs the 64x32 baseline.
// ===========================================================================

static __device__ float g_qkv[50331648];   // [32768][1536]  192 MB scratch
static __device__ float g_att[16777216];   // [32768][512]    64 MB scratch

__device__ __forceinline__ uint32_t f2tf(float f){
  uint32_t r; asm("cvt.rna.tf32.f32 %0, %1;" : "=r"(r) : "f"(f)); return r;
}

__device__ __forceinline__ void mma_tf32(float* c, const uint32_t* a, const uint32_t* b){
  asm volatile(
    "mma.sync.aligned.m16n8k8.row.col.f32.tf32.tf32.f32 "
    "{%0,%1,%2,%3}, {%4,%5,%6,%7}, {%8,%9}, {%0,%1,%2,%3};"
    : "+f"(c[0]), "+f"(c[1]), "+f"(c[2]), "+f"(c[3])
    : "r"(a[0]), "r"(a[1]), "r"(a[2]), "r"(a[3]), "r"(b[0]), "r"(b[1]));
}

// ---------------------------------------------------------------------------
// GEMM1: qkv = x-slice(M=32768,K=512 col-major) @ w_qkv(512,1536)
// As[2][16][136]  (bank = 8k+m, frag lanes 8t+g all distinct)
// Bs[2][16][264]  (bank = 8k+n, same property at N=256)
// ---------------------------------------------------------------------------
#define G1_AS(buf, k, m)  As[((buf)*16 + (k))*136 + (m)]
#define G1_BS(buf, k, n)  Bs[((buf)*16 + (k))*264 + (n)]
#define G1_SMEM ((2*16*136 + 2*16*264) * 4)

__global__ __launch_bounds__(256, 1) void gemm_qkv_kernel(
    const float* __restrict__ x, const float* __restrict__ w)
{
  extern __shared__ uint32_t sm1[];
  uint32_t* As = sm1;                 // [2][16][136]
  uint32_t* Bs = sm1 + 2*16*136;      // [2][16][264]

  const int nt = blockIdx.x;           // 0..5   (N tile, 256 cols)
  const int mt = blockIdx.y;           // 0..255 (M tile, 128 rows)
  const int f  = mt >> 4;
  const int sb = mt & 15;
  const int bb = sb >> 3;
  const int st = sb & 7;

  const float* Ab = x + (size_t)bb * 8388608 + f * 1024 + st * 128; // + k*16384 + m
  const float* Bb = w + nt * 256;                                   // + k*1536 + n

  const int tid  = threadIdx.x;
  const int lane = tid & 31, warp = tid >> 5;
  const int g = lane >> 2, t = lane & 3;
  const int mw = (warp & 1) << 6;      // 0,64
  const int nw = (warp >> 1) << 6;     // 0,64,128,192

  float acc[4][8][4];
  #pragma unroll
  for (int i = 0; i < 4; i++)
    #pragma unroll
    for (int j = 0; j < 8; j++)
      #pragma unroll
      for (int r = 0; r < 4; r++) acc[i][j][r] = 0.f;

  const int ak0 = tid >> 5;            // A k-row 0..7 (second: +8)
  const int aq0 = (tid & 31) << 2;     // float4 offset along m
  const int bk0 = tid >> 4;            // B k-row 0..15
  const int bq0 = (tid & 15) << 2;     // float4 offset along n (+64j)

  float4 ra0, ra1, rb[4];

  #define G1_FETCH(KT)                                                          \
    ra0 = *(const float4*)(Ab + (size_t)((KT)*16 + ak0    ) * 16384 + aq0);     \
    ra1 = *(const float4*)(Ab + (size_t)((KT)*16 + ak0 + 8) * 16384 + aq0);     \
    rb[0] = *(const float4*)(Bb + (size_t)((KT)*16 + bk0) * 1536 + bq0      );  \
    rb[1] = *(const float4*)(Bb + (size_t)((KT)*16 + bk0) * 1536 + bq0 +  64);  \
    rb[2] = *(const float4*)(Bb + (size_t)((KT)*16 + bk0) * 1536 + bq0 + 128);  \
    rb[3] = *(const float4*)(Bb + (size_t)((KT)*16 + bk0) * 1536 + bq0 + 192);

  #define G1_STAGE(BUF) {                                                       \
    uint4 u;                                                                    \
    u.x=f2tf(ra0.x); u.y=f2tf(ra0.y); u.z=f2tf(ra0.z); u.w=f2tf(ra0.w);         \
    *(uint4*)&G1_AS(BUF, ak0    , aq0) = u;                                     \
    u.x=f2tf(ra1.x); u.y=f2tf(ra1.y); u.z=f2tf(ra1.z); u.w=f2tf(ra1.w);         \
    *(uint4*)&G1_AS(BUF, ak0 + 8, aq0) = u;                                     \
    _Pragma("unroll")                                                           \
    for (int j = 0; j < 4; j++){                                                \
      u.x=f2tf(rb[j].x); u.y=f2tf(rb[j].y); u.z=f2tf(rb[j].z); u.w=f2tf(rb[j].w); \
      *(uint4*)&G1_BS(BUF, bk0, bq0 + 64*j) = u;                                \
    } }

  G1_FETCH(0);
  G1_STAGE(0);
  __syncthreads();

  #pragma unroll 1
  for (int kt = 0; kt < 32; kt++) {
    const int buf = kt & 1;
    if (kt < 31) { G1_FETCH(kt + 1); }

    #pragma unroll
    for (int ks = 0; ks < 2; ks++) {
      const int kb = ks * 8;
      uint32_t af[4][4], bf[8][2];
      #pragma unroll
      for (int mf = 0; mf < 4; mf++) {
        const int mb = mw + mf * 16 + g;
        af[mf][0] = G1_AS(buf, kb + t    , mb);
        af[mf][1] = G1_AS(buf, kb + t    , mb + 8);
        af[mf][2] = G1_AS(buf, kb + t + 4, mb);
        af[mf][3] = G1_AS(buf, kb + t + 4, mb + 8);
      }
      #pragma unroll
      for (int nf = 0; nf < 8; nf++) {
        const int nb = nw + nf * 8 + g;
        bf[nf][0] = G1_BS(buf, kb + t    , nb);
        bf[nf][1] = G1_BS(buf, kb + t + 4, nb);
      }
      #pragma unroll
      for (int mf = 0; mf < 4; mf++)
        #pragma unroll
        for (int nf = 0; nf < 8; nf++)
          mma_tf32(acc[mf][nf], af[mf], bf[nf]);
    }

    if (kt < 31) { G1_STAGE(buf ^ 1); }
    __syncthreads();
  }
  #undef G1_FETCH
  #undef G1_STAGE

  float* op = g_qkv + (size_t)(f * 2048 + bb * 1024 + st * 128) * 1536 + nt * 256;
  #pragma unroll
  for (int mf = 0; mf < 4; mf++) {
    const int r0 = mw + mf * 16 + g;
    #pragma unroll
    for (int nf = 0; nf < 8; nf++) {
      const int c0 = nw + nf * 8 + t * 2;
      *(float2*)(op + (size_t)r0 * 1536 + c0)       = make_float2(acc[mf][nf][0], acc[mf][nf][1]);
      *(float2*)(op + (size_t)(r0 + 8) * 1536 + c0) = make_float2(acc[mf][nf][2], acc[mf][nf][3]);
    }
  }
}

// ---------------------------------------------------------------------------
// Attention: one block per (s, head). q,k,v are 16x64; stable softmax + bias.
// ---------------------------------------------------------------------------
__global__ __launch_bounds__(128) void attn_kernel(const float* __restrict__ pos_bias)
{
  const int s = blockIdx.x;            // 0..2047
  const int h = blockIdx.y;            // 0..7

  __shared__ float qs[16][65];
  __shared__ float ks[16][65];
  __shared__ float vs[16][65];
  __shared__ float sim[16][16];

  const int tid = threadIdx.x;
  const int d   = tid & 63;
  const int f2  = tid >> 6;

  #pragma unroll
  for (int fi = 0; fi < 8; fi++) {
    const int f = fi * 2 + f2;
    const float* p = g_qkv + (size_t)(f * 2048 + s) * 1536 + h * 64 + d;
    qs[f][d] = p[0] * 0.125f;          // SCALE = 64^-0.5
    ks[f][d] = p[512];
    vs[f][d] = p[1024];
  }
  __syncthreads();

  #pragma unroll
  for (int e = tid; e < 256; e += 128) {
    const int i = e >> 4, j = e & 15;
    float a = 0.f;
    #pragma unroll
    for (int dd = 0; dd < 64; dd++) a += qs[i][dd] * ks[j][dd];
    sim[i][j] = a + pos_bias[h * 256 + i * 16 + j];
  }
  __syncthreads();

  if (tid < 16) {
    float m = sim[tid][0];
    #pragma unroll
    for (int j = 1; j < 16; j++) m = fmaxf(m, sim[tid][j]);
    float e[16], sum = 0.f;
    #pragma unroll
    for (int j = 0; j < 16; j++) { e[j] = expf(sim[tid][j] - m); sum += e[j]; }
    const float inv = 1.f / sum;
    #pragma unroll
    for (int j = 0; j < 16; j++) sim[tid][j] = e[j] * inv;
  }
  __syncthreads();

  #pragma unroll
  for (int fi = 0; fi < 8; fi++) {
    const int f = fi * 2 + f2;
    float o = 0.f;
    #pragma unroll
    for (int j = 0; j < 16; j++) o += sim[f][j] * vs[j][d];
    g_att[(size_t)(f * 2048 + s) * 512 + h * 64 + d] = o;
  }
}

// ---------------------------------------------------------------------------
// GEMM3: out = g_att(32768x512 row-major) @ w_out(512,512), scatter epilogue.
// As[2][128][28] (bank = 28m+k -> lanes -4g+t mod 32, all distinct)
// Bs[2][16][264]
// ---------------------------------------------------------------------------
#define G3_AS(buf, m, k)  As[((buf)*128 + (m))*28 + (k)]
#define G3_BS(buf, k, n)  Bs[((buf)*16 + (k))*264 + (n)]
#define G3_SMEM ((2*128*28 + 2*16*264) * 4)

__global__ __launch_bounds__(256, 1) void gemm_out_kernel(
    const float* __restrict__ w, float* __restrict__ out)
{
  extern __shared__ uint32_t sm3[];
  uint32_t* As = sm3;                  // [2][128][28]
  uint32_t* Bs = sm3 + 2*128*28;       // [2][16][264]

  const int nt = blockIdx.x;           // 0..1
  const int mt = blockIdx.y;           // 0..255

  const float* Ab = g_att + (size_t)mt * 128 * 512;
  const float* Bb = w + nt * 256;

  const int tid  = threadIdx.x;
  const int lane = tid & 31, warp = tid >> 5;
  const int g = lane >> 2, t = lane & 3;
  const int mw = (warp & 1) << 6;
  const int nw = (warp >> 1) << 6;

  float acc[4][8][4];
  #pragma unroll
  for (int i = 0; i < 4; i++)
    #pragma unroll
    for (int j = 0; j < 8; j++)
      #pragma unroll
      for (int r = 0; r < 4; r++) acc[i][j][r] = 0.f;

  const int ar0 = tid >> 1;            // A row 0..127
  const int ac0 = (tid & 1) << 3;      // k offset 0 or 8
  const int bk0 = tid >> 4;            // B k-row 0..15
  const int bq0 = (tid & 15) << 2;     // float4 offset along n (+64j)

  float4 ra0, ra1, rb[4];

  #define G3_FETCH(KT)                                                          \
    ra0 = *(const float4*)(Ab + (size_t)ar0 * 512 + (KT)*16 + ac0    );         \
    ra1 = *(const float4*)(Ab + (size_t)ar0 * 512 + (KT)*16 + ac0 + 4);         \
    rb[0] = *(const float4*)(Bb + (size_t)((KT)*16 + bk0) * 512 + bq0      );   \
    rb[1] = *(const float4*)(Bb + (size_t)((KT)*16 + bk0) * 512 + bq0 +  64);   \
    rb[2] = *(const float4*)(Bb + (size_t)((KT)*16 + bk0) * 512 + bq0 + 128);   \
    rb[3] = *(const float4*)(Bb + (size_t)((KT)*16 + bk0) * 512 + bq0 + 192);

  #define G3_STAGE(BUF) {                                                       \
    uint4 u;                                                                    \
    u.x=f2tf(ra0.x); u.y=f2tf(ra0.y); u.z=f2tf(ra0.z); u.w=f2tf(ra0.w);         \
    *(uint4*)&G3_AS(BUF, ar0, ac0    ) = u;                                     \
    u.x=f2tf(ra1.x); u.y=f2tf(ra1.y); u.z=f2tf(ra1.z); u.w=f2tf(ra1.w);         \
    *(uint4*)&G3_AS(BUF, ar0, ac0 + 4) = u;                                     \
    _Pragma("unroll")                                                           \
    for (int j = 0; j < 4; j++){                                                \
      u.x=f2tf(rb[j].x); u.y=f2tf(rb[j].y); u.z=f2tf(rb[j].z); u.w=f2tf(rb[j].w); \
      *(uint4*)&G3_BS(BUF, bk0, bq0 + 64*j) = u;                                \
    } }

  G3_FETCH(0);
  G3_STAGE(0);
  __syncthreads();

  #pragma unroll 1
  for (int kt = 0; kt < 32; kt++) {
    const int buf = kt & 1;
    if (kt < 31) { G3_FETCH(kt + 1); }

    #pragma unroll
    for (int ks = 0; ks < 2; ks++) {
      const int kb = ks * 8;
      uint32_t af[4][4], bf[8][2];
      #pragma unroll
      for (int mf = 0; mf < 4; mf++) {
        const int mb = mw + mf * 16 + g;
        af[mf][0] = G3_AS(buf, mb    , kb + t);
        af[mf][1] = G3_AS(buf, mb + 8, kb + t);
        af[mf][2] = G3_AS(buf, mb    , kb + t + 4);
        af[mf][3] = G3_AS(buf, mb + 8, kb + t + 4);
      }
      #pragma unroll
      for (int nf = 0; nf < 8; nf++) {
        const int nb = nw + nf * 8 + g;
        bf[nf][0] = G3_BS(buf, kb + t    , nb);
        bf[nf][1] = G3_BS(buf, kb + t + 4, nb);
      }
      #pragma unroll
      for (int mf = 0; mf < 4; mf++)
        #pragma unroll
        for (int nf = 0; nf < 8; nf++)
          mma_tf32(acc[mf][nf], af[mf], bf[nf]);
    }

    if (kt < 31) { G3_STAGE(buf ^ 1); }
    __syncthreads();
  }
  #undef G3_FETCH
  #undef G3_STAGE

  // row = mt*128 + local = f*2048 + bb*1024 + sl
  #pragma unroll
  for (int mf = 0; mf < 4; mf++) {
    const int r0 = mt * 128 + mw + mf * 16 + g;
    const int f0  = r0 >> 11;
    const int bb0 = (r0 >> 10) & 1;
    const int sl0 = r0 & 1023;
    float* ob0 = out + (size_t)bb0 * 8388608 + f0 * 1024 + sl0;
    const int r1 = r0 + 8;             // same f/bb block (128-row tile, 16-aligned)
    float* ob1 = ob0 + 8;
    #pragma unroll
    for (int nf = 0; nf < 8; nf++) {
      const int c0 = nt * 256 + nw + nf * 8 + t * 2;
      ob0[(size_t)(c0    ) * 16384] = acc[mf][nf][0];
      ob0[(size_t)(c0 + 1) * 16384] = acc[mf][nf][1];
      ob1[(size_t)(c0    ) * 16384] = acc[mf][nf][2];
      ob1[(size_t)(c0 + 1) * 16384] = acc[mf][nf][3];
    }
    (void)r1;
  }
}

// ---------------------------------------------------------------------------
extern "C" void kernel_launch(void* const* d_in, const int* in_sizes, int n_in,
                              void* d_out, int out_size)
{
  (void)in_sizes; (void)n_in; (void)out_size;
  const float* x  = (const float*)d_in[0];
  const float* pb = (const float*)d_in[1];
  const float* wq = (const float*)d_in[2];
  const float* wo = (const float*)d_in[3];
  float* out = (float*)d_out;

  static int attr_done = 0;
  if (!attr_done) {
    cudaFuncSetAttribute(gemm_qkv_kernel, cudaFuncAttributeMaxDynamicSharedMemorySize, G1_SMEM);
    cudaFuncSetAttribute(gemm_out_kernel, cudaFuncAttributeMaxDynamicSharedMemorySize, G3_SMEM);
    attr_done = 1;
  }

  dim3 g1(6, 256);   gemm_qkv_kernel<<<g1, 256, G1_SMEM>>>(x, wq);
  dim3 ga(2048, 8);  attn_kernel<<<ga, 128>>>(pb);
  dim3 g3(2, 256);   gemm_out_kernel<<<g3, 256, G3_SMEM>>>(wo, out);
}

// round 10
// speedup vs baseline: 1.3566x; 1.3566x over previous
#include <cuda_runtime.h>
#include <cuda_fp16.h>
#include <cstdint>

// ===========================================================================
// TemporalAttention — fp16 mma.sync (m16n8k16, fp32 accumulate) GEMMs.
// tf32 m16n8k8 was pinned at the MMA dispatch-rate ceiling (~16 cyc/SMSP);
// fp16 m16n8k16 carries 2x FLOP per dispatched instruction at equal mantissa
// width (10 bits), so accuracy is unchanged (~5e-4) while halving MMA count.
//
//   s = b*1024 + hh*32 + ww   (spatial index, 2048 total)
//   x[b][c][f][hh][ww] flat = b*8388608 + c*16384 + f*1024 + s_local
//   g_qkv[(f*2048 + s)][n]  n in [0,1536): q|k|v each 512 (f-major rows, fp32)
//   g_att_h[(f*2048 + s)][j] fp16
//
// GEMM CTA tile 128(M) x 256(N), 8 warps 2x4, warp tile 64x64, K-step 16.
// SMEM holds half2-packed operands: As[k2][m], Bs[k2][n], k2 = k/2.
// ===========================================================================

static __device__ float  g_qkv[50331648];    // [32768][1536] fp32, 192 MB
static __device__ __half g_att_h[16777216];  // [32768][512]  fp16,  32 MB

__device__ __forceinline__ uint32_t pk(float lo, float hi){
  // pack: low 16 bits = lo (even k), high = hi (odd k)
  uint32_t r; asm("cvt.rn.f16x2.f32 %0, %2, %1;" : "=r"(r) : "f"(lo), "f"(hi));
  return r;
}

__device__ __forceinline__ void mma_f16(float* c, const uint32_t* a, const uint32_t* b){
  asm volatile(
    "mma.sync.aligned.m16n8k16.row.col.f32.f16.f16.f32 "
    "{%0,%1,%2,%3}, {%4,%5,%6,%7}, {%8,%9}, {%0,%1,%2,%3};"
    : "+f"(c[0]), "+f"(c[1]), "+f"(c[2]), "+f"(c[3])
    : "r"(a[0]), "r"(a[1]), "r"(a[2]), "r"(a[3]), "r"(b[0]), "r"(b[1]));
}

// ---------------------------------------------------------------------------
// GEMM1: qkv = x-slice(M=32768,K=512 col-major) @ w_qkv(512,1536)
// As[2][8][136] uint32(half2): bank = 8*k2 + m  -> frag lanes 8t+g distinct
// Bs[2][8][264]              : bank = 8*k2 + n  -> same property
// ---------------------------------------------------------------------------
__global__ __launch_bounds__(256, 1) void gemm_qkv_kernel(
    const float* __restrict__ x, const float* __restrict__ w)
{
  __shared__ __align__(16) uint32_t As[2][8][136];
  __shared__ __align__(16) uint32_t Bs[2][8][264];

  const int nt = blockIdx.x;           // 0..5   (N tile, 256 cols)
  const int mt = blockIdx.y;           // 0..255 (M tile, 128 rows)
  const int f  = mt >> 4;
  const int sb = mt & 15;
  const int bb = sb >> 3;
  const int st = sb & 7;

  const float* Ab = x + (size_t)bb * 8388608 + f * 1024 + st * 128; // + k*16384 + m
  const float* Bb = w + nt * 256;                                   // + k*1536 + n

  const int tid  = threadIdx.x;
  const int lane = tid & 31, warp = tid >> 5;
  const int g = lane >> 2, t = lane & 3;
  const int mw = (warp & 1) << 6;      // 0,64
  const int nw = (warp >> 1) << 6;     // 0,64,128,192

  float acc[4][8][4];
  #pragma unroll
  for (int i = 0; i < 4; i++)
    #pragma unroll
    for (int j = 0; j < 8; j++)
      #pragma unroll
      for (int r = 0; r < 4; r++) acc[i][j][r] = 0.f;

  const int ak0 = tid >> 5;            // k2 row 0..7
  const int aq0 = (tid & 31) << 2;     // m float4 offset
  const int bq0 = (tid & 31) << 2;     // n float4 offset (segments +0,+128)

  float4 ra0, ra1, rb00, rb10, rb01, rb11;

  #define G1_FETCH(KT)                                                          \
    ra0  = *(const float4*)(Ab + (size_t)((KT)*16 + 2*ak0    ) * 16384 + aq0);  \
    ra1  = *(const float4*)(Ab + (size_t)((KT)*16 + 2*ak0 + 1) * 16384 + aq0);  \
    rb00 = *(const float4*)(Bb + (size_t)((KT)*16 + 2*ak0    ) * 1536 + bq0);   \
    rb10 = *(const float4*)(Bb + (size_t)((KT)*16 + 2*ak0 + 1) * 1536 + bq0);   \
    rb01 = *(const float4*)(Bb + (size_t)((KT)*16 + 2*ak0    ) * 1536 + bq0 + 128); \
    rb11 = *(const float4*)(Bb + (size_t)((KT)*16 + 2*ak0 + 1) * 1536 + bq0 + 128);

  #define G1_STAGE(BUF) {                                                       \
    uint4 u;                                                                    \
    u.x=pk(ra0.x,ra1.x); u.y=pk(ra0.y,ra1.y);                                   \
    u.z=pk(ra0.z,ra1.z); u.w=pk(ra0.w,ra1.w);                                   \
    *(uint4*)&As[BUF][ak0][aq0] = u;                                            \
    u.x=pk(rb00.x,rb10.x); u.y=pk(rb00.y,rb10.y);                               \
    u.z=pk(rb00.z,rb10.z); u.w=pk(rb00.w,rb10.w);                               \
    *(uint4*)&Bs[BUF][ak0][bq0] = u;                                            \
    u.x=pk(rb01.x,rb11.x); u.y=pk(rb01.y,rb11.y);                               \
    u.z=pk(rb01.z,rb11.z); u.w=pk(rb01.w,rb11.w);                               \
    *(uint4*)&Bs[BUF][ak0][bq0 + 128] = u; }

  G1_FETCH(0);
  G1_STAGE(0);
  __syncthreads();

  #pragma unroll 1
  for (int kt = 0; kt < 32; kt++) {
    const int buf = kt & 1;
    if (kt < 31) { G1_FETCH(kt + 1); }

    uint32_t af[4][4], bf[8][2];
    #pragma unroll
    for (int mf = 0; mf < 4; mf++) {
      const int mb = mw + mf * 16 + g;
      af[mf][0] = As[buf][t    ][mb];
      af[mf][1] = As[buf][t    ][mb + 8];
      af[mf][2] = As[buf][t + 4][mb];
      af[mf][3] = As[buf][t + 4][mb + 8];
    }
    #pragma unroll
    for (int nf = 0; nf < 8; nf++) {
      const int nb = nw + nf * 8 + g;
      bf[nf][0] = Bs[buf][t    ][nb];
      bf[nf][1] = Bs[buf][t + 4][nb];
    }
    #pragma unroll
    for (int mf = 0; mf < 4; mf++)
      #pragma unroll
      for (int nf = 0; nf < 8; nf++)
        mma_f16(acc[mf][nf], af[mf], bf[nf]);

    if (kt < 31) { G1_STAGE(buf ^ 1); }
    __syncthreads();
  }
  #undef G1_FETCH
  #undef G1_STAGE

  float* op = g_qkv + (size_t)(f * 2048 + bb * 1024 + st * 128) * 1536 + nt * 256;
  #pragma unroll
  for (int mf = 0; mf < 4; mf++) {
    const int r0 = mw + mf * 16 + g;
    #pragma unroll
    for (int nf = 0; nf < 8; nf++) {
      const int c0 = nw + nf * 8 + t * 2;
      *(float2*)(op + (size_t)r0 * 1536 + c0)       = make_float2(acc[mf][nf][0], acc[mf][nf][1]);
      *(float2*)(op + (size_t)(r0 + 8) * 1536 + c0) = make_float2(acc[mf][nf][2], acc[mf][nf][3]);
    }
  }
}

// ---------------------------------------------------------------------------
// Attention: one block per (s, head). fp32 math, fp16 output.
// ---------------------------------------------------------------------------
__global__ __launch_bounds__(128) void attn_kernel(const float* __restrict__ pos_bias)
{
  const int s = blockIdx.x;            // 0..2047
  const int h = blockIdx.y;            // 0..7

  __shared__ float qs[16][65];
  __shared__ float ks[16][65];
  __shared__ float vs[16][65];
  __shared__ float sim[16][16];

  const int tid = threadIdx.x;
  const int d   = tid & 63;
  const int f2  = tid >> 6;

  #pragma unroll
  for (int fi = 0; fi < 8; fi++) {
    const int f = fi * 2 + f2;
    const float* p = g_qkv + (size_t)(f * 2048 + s) * 1536 + h * 64 + d;
    qs[f][d] = p[0] * 0.125f;          // SCALE = 64^-0.5
    ks[f][d] = p[512];
    vs[f][d] = p[1024];
  }
  __syncthreads();

  #pragma unroll
  for (int e = tid; e < 256; e += 128) {
    const int i = e >> 4, j = e & 15;
    float a = 0.f;
    #pragma unroll
    for (int dd = 0; dd < 64; dd++) a += qs[i][dd] * ks[j][dd];
    sim[i][j] = a + pos_bias[h * 256 + i * 16 + j];
  }
  __syncthreads();

  if (tid < 16) {
    float m = sim[tid][0];
    #pragma unroll
    for (int j = 1; j < 16; j++) m = fmaxf(m, sim[tid][j]);
    float e[16], sum = 0.f;
    #pragma unroll
    for (int j = 0; j < 16; j++) { e[j] = expf(sim[tid][j] - m); sum += e[j]; }
    const float inv = 1.f / sum;
    #pragma unroll
    for (int j = 0; j < 16; j++) sim[tid][j] = e[j] * inv;
  }
  __syncthreads();

  #pragma unroll
  for (int fi = 0; fi < 8; fi++) {
    const int f = fi * 2 + f2;
    float o = 0.f;
    #pragma unroll
    for (int j = 0; j < 16; j++) o += sim[f][j] * vs[j][d];
    g_att_h[(size_t)(f * 2048 + s) * 512 + h * 64 + d] = __float2half(o);
  }
}

// ---------------------------------------------------------------------------
// GEMM3: out = g_att_h(32768x512, fp16 row-major) @ w_out(512,512), scatter.
// As[2][128][12] uint32(half2) A[m][k2]: frag bank = 12g+t all distinct.
// Bs[2][8][264].
// ---------------------------------------------------------------------------
__global__ __launch_bounds__(256, 1) void gemm_out_kernel(
    const float* __restrict__ w, float* __restrict__ out)
{
  __shared__ __align__(16) uint32_t As[2][128][12];
  __shared__ __align__(16) uint32_t Bs[2][8][264];

  const int nt = blockIdx.x;           // 0..1
  const int mt = blockIdx.y;           // 0..255

  const __half* Ah = g_att_h + (size_t)mt * 128 * 512;
  const float*  Bb = w + nt * 256;

  const int tid  = threadIdx.x;
  const int lane = tid & 31, warp = tid >> 5;
  const int g = lane >> 2, t = lane & 3;
  const int mw = (warp & 1) << 6;
  const int nw = (warp >> 1) << 6;

  float acc[4][8][4];
  #pragma unroll
  for (int i = 0; i < 4; i++)
    #pragma unroll
    for (int j = 0; j < 8; j++)
      #pragma unroll
      for (int r = 0; r < 4; r++) acc[i][j][r] = 0.f;

  const int ar0 = tid >> 1;            // A row 0..127
  const int ac0 = (tid & 1) << 2;      // k2 offset 0 or 4
  const int bk0 = tid >> 5;            // k2 row 0..7
  const int bq0 = (tid & 31) << 2;     // n offset (segments +0,+128)

  uint4 ua;
  float4 rb00, rb10, rb01, rb11;

  #define G3_FETCH(KT)                                                          \
    ua   = *(const uint4*)(Ah + (size_t)ar0 * 512 + (KT)*16 + ac0 * 2);         \
    rb00 = *(const float4*)(Bb + (size_t)((KT)*16 + 2*bk0    ) * 512 + bq0);    \
    rb10 = *(const float4*)(Bb + (size_t)((KT)*16 + 2*bk0 + 1) * 512 + bq0);    \
    rb01 = *(const float4*)(Bb + (size_t)((KT)*16 + 2*bk0    ) * 512 + bq0 + 128); \
    rb11 = *(const float4*)(Bb + (size_t)((KT)*16 + 2*bk0 + 1) * 512 + bq0 + 128);

  #define G3_STAGE(BUF) {                                                       \
    *(uint4*)&As[BUF][ar0][ac0] = ua;                                           \
    uint4 u;                                                                    \
    u.x=pk(rb00.x,rb10.x); u.y=pk(rb00.y,rb10.y);                               \
    u.z=pk(rb00.z,rb10.z); u.w=pk(rb00.w,rb10.w);                               \
    *(uint4*)&Bs[BUF][bk0][bq0] = u;                                            \
    u.x=pk(rb01.x,rb11.x); u.y=pk(rb01.y,rb11.y);                               \
    u.z=pk(rb01.z,rb11.z); u.w=pk(rb01.w,rb11.w);                               \
    *(uint4*)&Bs[BUF][bk0][bq0 + 128] = u; }

  G3_FETCH(0);
  G3_STAGE(0);
  __syncthreads();

  #pragma unroll 1
  for (int kt = 0; kt < 32; kt++) {
    const int buf = kt & 1;
    if (kt < 31) { G3_FETCH(kt + 1); }

    uint32_t af[4][4], bf[8][2];
    #pragma unroll
    for (int mf = 0; mf < 4; mf++) {
      const int mb = mw + mf * 16 + g;
      af[mf][0] = As[buf][mb    ][t];
      af[mf][1] = As[buf][mb + 8][t];
      af[mf][2] = As[buf][mb    ][t + 4];
      af[mf][3] = As[buf][mb + 8][t + 4];
    }
    #pragma unroll
    for (int nf = 0; nf < 8; nf++) {
      const int nb = nw + nf * 8 + g;
      bf[nf][0] = Bs[buf][t    ][nb];
      bf[nf][1] = Bs[buf][t + 4][nb];
    }
    #pragma unroll
    for (int mf = 0; mf < 4; mf++)
      #pragma unroll
      for (int nf = 0; nf < 8; nf++)
        mma_f16(acc[mf][nf], af[mf], bf[nf]);

    if (kt < 31) { G3_STAGE(buf ^ 1); }
    __syncthreads();
  }
  #undef G3_FETCH
  #undef G3_STAGE

  // row = mt*128 + local = f*2048 + bb*1024 + sl
  #pragma unroll
  for (int mf = 0; mf < 4; mf++) {
    const int r0 = mt * 128 + mw + mf * 16 + g;
    const int f0  = r0 >> 11;
    const int bb0 = (r0 >> 10) & 1;
    const int sl0 = r0 & 1023;
    float* ob0 = out + (size_t)bb0 * 8388608 + f0 * 1024 + sl0;
    float* ob1 = ob0 + 8;              // r0+8 stays in the same f/bb block
    #pragma unroll
    for (int nf = 0; nf < 8; nf++) {
      const int c0 = nt * 256 + nw + nf * 8 + t * 2;
      ob0[(size_t)(c0    ) * 16384] = acc[mf][nf][0];
      ob0[(size_t)(c0 + 1) * 16384] = acc[mf][nf][1];
      ob1[(size_t)(c0    ) * 16384] = acc[mf][nf][2];
      ob1[(size_t)(c0 + 1) * 16384] = acc[mf][nf][3];
    }
  }
}

// ---------------------------------------------------------------------------
extern "C" void kernel_launch(void* const* d_in, const int* in_sizes, int n_in,
                              void* d_out, int out_size)
{
  (void)in_sizes; (void)n_in; (void)out_size;
  const float* x  = (const float*)d_in[0];
  const float* pb = (const float*)d_in[1];
  const float* wq = (const float*)d_in[2];
  const float* wo = (const float*)d_in[3];
  float* out = (float*)d_out;

  dim3 g1(6, 256);   gemm_qkv_kernel<<<g1, 256>>>(x, wq);
  dim3 ga(2048, 8);  attn_kernel<<<ga, 128>>>(pb);
  dim3 g3(2, 256);   gemm_out_kernel<<<g3, 256>>>(wo, out);
}

// round 13
// speedup vs baseline: 1.7469x; 1.2877x over previous
#include <cuda_runtime.h>
#include <cuda_fp16.h>
#include <cstdint>

// ===========================================================================
// TemporalAttention — fp16 mma.sync m16n8k16 + cp.async 4-stage pipeline.
//
// Pre-pass packs x and weights into half2 [k2][·] gmem layouts so GEMM
// staging is a pure 16B cp.async copy (no cvt, no register round-trip in the
// hot loop). qkv intermediate is fp16 (96 MB).
//
//   m row index = f*2048 + bb*1024 + sl   (m0 = mt*128)
//   x[b][c][f][hh][ww] flat = b*8388608 + c*16384 + f*1024 + sl
// ===========================================================================

static __device__ uint32_t g_xh  [ 8388608];   // [256][32768] half2(k,k+1), 32 MB
static __device__ uint32_t g_wqh [  393216];   // [256][1536]
static __device__ uint32_t g_woh [  131072];   // [256][512]
static __device__ __half   g_qkv_h[50331648];  // [32768][1536]  96 MB
static __device__ __half   g_att_h[16777216];  // [32768][512]   32 MB

__device__ __forceinline__ uint32_t pk(float lo, float hi){
  uint32_t r; asm("cvt.rn.f16x2.f32 %0, %2, %1;" : "=r"(r) : "f"(lo), "f"(hi));
  return r;
}
__device__ __forceinline__ uint32_t smem_u32(const void* p){
  uint32_t a;
  asm("{ .reg .u64 t; cvta.to.shared.u64 t, %1; cvt.u32.u64 %0, t; }" : "=r"(a) : "l"(p));
  return a;
}
__device__ __forceinline__ void mma_f16(float* c, const uint32_t* a, const uint32_t* b){
  asm volatile(
    "mma.sync.aligned.m16n8k16.row.col.f32.f16.f16.f32 "
    "{%0,%1,%2,%3}, {%4,%5,%6,%7}, {%8,%9}, {%0,%1,%2,%3};"
    : "+f"(c[0]), "+f"(c[1]), "+f"(c[2]), "+f"(c[3])
    : "r"(a[0]), "r"(a[1]), "r"(a[2]), "r"(a[3]), "r"(b[0]), "r"(b[1]));
}

#define CP_ASYNC16(dst, src) \
  asm volatile("cp.async.cg.shared.global [%0], [%1], 16;" :: "r"(dst), "l"(src))
#define CP_COMMIT() asm volatile("cp.async.commit_group;" ::: "memory")
#define CP_WAIT2()  asm volatile("cp.async.wait_group 2;" ::: "memory")

// ---------------- pre-pack kernels -----------------------------------------
// x -> g_xh[k2][m]: half2( x(2k2, m), x(2k2+1, m) ), m = f*2048+bb*1024+sl
__global__ __launch_bounds__(256) void pack_x_kernel(const float* __restrict__ x)
{
  const int k2 = blockIdx.x;           // 0..255
  const int mb = blockIdx.y;           // 0..31
  const int f  = mb >> 1;
  const int bb = mb & 1;
  const float* p0 = x + (size_t)bb * 8388608 + (size_t)(2 * k2) * 16384 + f * 1024;
  uint32_t* dst = g_xh + (size_t)k2 * 32768 + mb * 1024;
  #pragma unroll
  for (int i = 0; i < 4; i++){
    const int sl = i * 256 + threadIdx.x;
    dst[sl] = pk(p0[sl], p0[sl + 16384]);
  }
}

// w[512][ncols] -> dst[256][ncols] half2 along k
__global__ __launch_bounds__(256) void pack_w_kernel(
    const float* __restrict__ w, uint32_t* __restrict__ dst, int ncols)
{
  const int id = blockIdx.x * 256 + threadIdx.x;   // k2*ncols + n
  const int k2 = id / ncols, n = id - k2 * ncols;
  dst[id] = pk(w[(size_t)(2 * k2) * ncols + n], w[(size_t)(2 * k2 + 1) * ncols + n]);
}

// ---------------------------------------------------------------------------
// GEMM1: qkv_h = x(32768x512) @ w_qkv(512x1536), CTA 128x256, 8 warps 2x4,
// warp tile 64x64, K-step 16 (8 half2 rows). 4-stage cp.async pipeline.
// Stage layout (uint32): A[8][136] then B[8][264]  (3200 u32 = 12.8 KB)
// ---------------------------------------------------------------------------
#define G1_STAGE_U32 3200
#define G1_SMEM      (4 * G1_STAGE_U32 * 4)

__global__ __launch_bounds__(256, 1) void gemm_qkv_kernel()
{
  extern __shared__ uint32_t sm[];
  const uint32_t smem_base = smem_u32(sm);

  const int nt = blockIdx.x;           // 0..5
  const int mt = blockIdx.y;           // 0..255
  const int m0 = mt * 128, n0 = nt * 256;

  const int tid  = threadIdx.x;
  const int lane = tid & 31, warp = tid >> 5;
  const int g = lane >> 2, t = lane & 3;
  const int mw = (warp & 1) << 6;
  const int nw = (warp >> 1) << 6;

  // staging chunk map: thread -> 1 A chunk + 2 B chunks (16B each)
  const int a_row = tid >> 5, a_col = (tid & 31) << 2;           // A: 8 x 32 chunks
  const int b1row = tid >> 6, b1col = (tid & 63) << 2;           // B: 8 x 64 chunks
  const int b2row = b1row + 4, b2col = b1col;

  const uint32_t* Asrc = g_xh  + m0 + a_col;
  const uint32_t* B1   = g_wqh + n0 + b1col;
  const uint32_t* B2   = g_wqh + n0 + b2col;

  #define G1_DO_STAGE(KT) {                                                     \
    const uint32_t sb = smem_base + (uint32_t)((KT) & 3) * (G1_STAGE_U32 * 4);  \
    CP_ASYNC16(sb + (uint32_t)(a_row * 136 + a_col) * 4,                        \
               Asrc + (size_t)((KT) * 8 + a_row) * 32768);                      \
    CP_ASYNC16(sb + (uint32_t)(1088 + b1row * 264 + b1col) * 4,                 \
               B1 + (size_t)((KT) * 8 + b1row) * 1536);                         \
    CP_ASYNC16(sb + (uint32_t)(1088 + b2row * 264 + b2col) * 4,                 \
               B2 + (size_t)((KT) * 8 + b2row) * 1536); }

  float acc[4][8][4];
  #pragma unroll
  for (int i = 0; i < 4; i++)
    #pragma unroll
    for (int j = 0; j < 8; j++)
      #pragma unroll
      for (int r = 0; r < 4; r++) acc[i][j][r] = 0.f;

  G1_DO_STAGE(0); CP_COMMIT();
  G1_DO_STAGE(1); CP_COMMIT();
  G1_DO_STAGE(2); CP_COMMIT();

  #pragma unroll 1
  for (int kt = 0; kt < 32; kt++) {
    CP_WAIT2();
    __syncthreads();

    const uint32_t* AS = sm + (kt & 3) * G1_STAGE_U32;
    const uint32_t* BS = AS + 1088;

    uint32_t af[4][4], bf[8][2];
    #pragma unroll
    for (int mf = 0; mf < 4; mf++) {
      const int mb = mw + mf * 16 + g;
      af[mf][0] = AS[t * 136 + mb];
      af[mf][1] = AS[t * 136 + mb + 8];
      af[mf][2] = AS[(t + 4) * 136 + mb];
      af[mf][3] = AS[(t + 4) * 136 + mb + 8];
    }
    #pragma unroll
    for (int nf = 0; nf < 8; nf++) {
      const int nb = nw + nf * 8 + g;
      bf[nf][0] = BS[t * 264 + nb];
      bf[nf][1] = BS[(t + 4) * 264 + nb];
    }
    #pragma unroll
    for (int mf = 0; mf < 4; mf++)
      #pragma unroll
      for (int nf = 0; nf < 8; nf++)
        mma_f16(acc[mf][nf], af[mf], bf[nf]);

    if (kt + 3 < 32) { G1_DO_STAGE(kt + 3); }
    CP_COMMIT();
  }
  #undef G1_DO_STAGE

  // epilogue: fp16 output, adjacent n-pairs packed
  uint32_t* oph = (uint32_t*)g_qkv_h;  // row pitch 768 u32
  #pragma unroll
  for (int mf = 0; mf < 4; mf++) {
    const int r0 = m0 + mw + mf * 16 + g;
    #pragma unroll
    for (int nf = 0; nf < 8; nf++) {
      const int c2 = nt * 128 + (nw + nf * 8 + t * 2) / 2;
      oph[(size_t)r0 * 768 + c2]       = pk(acc[mf][nf][0], acc[mf][nf][1]);
      oph[(size_t)(r0 + 8) * 768 + c2] = pk(acc[mf][nf][2], acc[mf][nf][3]);
    }
  }
}

// ---------------------------------------------------------------------------
// Attention: one block per (s, head). fp16 in, fp32 math, fp16 out.
// ---------------------------------------------------------------------------
__global__ __launch_bounds__(128) void attn_kernel(const float* __restrict__ pos_bias)
{
  const int s = blockIdx.x;            // 0..2047
  const int h = blockIdx.y;            // 0..7

  __shared__ float qs[16][65];
  __shared__ float ks[16][65];
  __shared__ float vs[16][65];
  __shared__ float sim[16][16];

  const int tid = threadIdx.x;
  const int d   = tid & 63;
  const int f2  = tid >> 6;

  #pragma unroll
  for (int fi = 0; fi < 8; fi++) {
    const int f = fi * 2 + f2;
    const __half* p = g_qkv_h + (size_t)(f * 2048 + s) * 1536 + h * 64 + d;
    qs[f][d] = __half2float(p[0]) * 0.125f;     // SCALE = 64^-0.5
    ks[f][d] = __half2float(p[512]);
    vs[f][d] = __half2float(p[1024]);
  }
  __syncthreads();

  #pragma unroll
  for (int e = tid; e < 256; e += 128) {
    const int i = e >> 4, j = e & 15;
    float a = 0.f;
    #pragma unroll
    for (int dd = 0; dd < 64; dd++) a += qs[i][dd] * ks[j][dd];
    sim[i][j] = a + pos_bias[h * 256 + i * 16 + j];
  }
  __syncthreads();

  if (tid < 16) {
    float m = sim[tid][0];
    #pragma unroll
    for (int j = 1; j < 16; j++) m = fmaxf(m, sim[tid][j]);
    float e[16], sum = 0.f;
    #pragma unroll
    for (int j = 0; j < 16; j++) { e[j] = expf(sim[tid][j] - m); sum += e[j]; }
    const float inv = 1.f / sum;
    #pragma unroll
    for (int j = 0; j < 16; j++) sim[tid][j] = e[j] * inv;
  }
  __syncthreads();

  #pragma unroll
  for (int fi = 0; fi < 8; fi++) {
    const int f = fi * 2 + f2;
    float o = 0.f;
    #pragma unroll
    for (int j = 0; j < 16; j++) o += sim[f][j] * vs[j][d];
    g_att_h[(size_t)(f * 2048 + s) * 512 + h * 64 + d] = __float2half(o);
  }
}

// ---------------------------------------------------------------------------
// GEMM3: out = g_att_h(32768x512) @ w_out(512x512), scatter epilogue.
// Stage layout (uint32): A[128][12] (1536) then B[8][264] (2112) = 3648 u32.
// ---------------------------------------------------------------------------
#define G3_STAGE_U32 3648
#define G3_SMEM      (4 * G3_STAGE_U32 * 4)

__global__ __launch_bounds__(256, 1) void gemm_out_kernel(float* __restrict__ out)
{
  extern __shared__ uint32_t sm[];
  const uint32_t smem_base = smem_u32(sm);

  const int nt = blockIdx.x;           // 0..1
  const int mt = blockIdx.y;           // 0..255
  const int n0 = nt * 256;

  const int tid  = threadIdx.x;
  const int lane = tid & 31, warp = tid >> 5;
  const int g = lane >> 2, t = lane & 3;
  const int mw = (warp & 1) << 6;
  const int nw = (warp >> 1) << 6;

  // staging chunk map: A 256 chunks (row=tid>>1, col=tid&1) + B 512 chunks
  const int a_row = tid >> 1, a_col = (tid & 1) << 2;            // A[m][k2]: 8 u32/row
  const int b1row = tid >> 6, b1col = (tid & 63) << 2;
  const int b2row = b1row + 4, b2col = b1col;

  const uint32_t* Asrc = (const uint32_t*)g_att_h + (size_t)(mt * 128 + a_row) * 256 + a_col;
  const uint32_t* B1   = g_woh + n0 + b1col;
  const uint32_t* B2   = g_woh + n0 + b2col;

  #define G3_DO_STAGE(KT) {                                                     \
    const uint32_t sb = smem_base + (uint32_t)((KT) & 3) * (G3_STAGE_U32 * 4);  \
    CP_ASYNC16(sb + (uint32_t)(a_row * 12 + a_col) * 4,                         \
               Asrc + (KT) * 8);                                                \
    CP_ASYNC16(sb + (uint32_t)(1536 + b1row * 264 + b1col) * 4,                 \
               B1 + (size_t)((KT) * 8 + b1row) * 512);                          \
    CP_ASYNC16(sb + (uint32_t)(1536 + b2row * 264 + b2col) * 4,                 \
               B2 + (size_t)((KT) * 8 + b2row) * 512); }

  float acc[4][8][4];
  #pragma unroll
  for (int i = 0; i < 4; i++)
    #pragma unroll
    for (int j = 0; j < 8; j++)
      #pragma unroll
      for (int r = 0; r < 4; r++) acc[i][j][r] = 0.f;

  G3_DO_STAGE(0); CP_COMMIT();
  G3_DO_STAGE(1); CP_COMMIT();
  G3_DO_STAGE(2); CP_COMMIT();

  #pragma unroll 1
  for (int kt = 0; kt < 32; kt++) {
    CP_WAIT2();
    __syncthreads();

    const uint32_t* AS = sm + (kt & 3) * G3_STAGE_U32;
    const uint32_t* BS = AS + 1536;

    uint32_t af[4][4], bf[8][2];
    #pragma unroll
    for (int mf = 0; mf < 4; mf++) {
      const int mb = mw + mf * 16 + g;
      af[mf][0] = AS[mb * 12 + t];
      af[mf][1] = AS[(mb + 8) * 12 + t];
      af[mf][2] = AS[mb * 12 + t + 4];
      af[mf][3] = AS[(mb + 8) * 12 + t + 4];
    }
    #pragma unroll
    for (int nf = 0; nf < 8; nf++) {
      const int nb = nw + nf * 8 + g;
      bf[nf][0] = BS[t * 264 + nb];
      bf[nf][1] = BS[(t + 4) * 264 + nb];
    }
    #pragma unroll
    for (int mf = 0; mf < 4; mf++)
      #pragma unroll
      for (int nf = 0; nf < 8; nf++)
        mma_f16(acc[mf][nf], af[mf], bf[nf]);

    if (kt + 3 < 32) { G3_DO_STAGE(kt + 3); }
    CP_COMMIT();
  }
  #undef G3_DO_STAGE

  // scatter: row = mt*128 + local = f*2048 + bb*1024 + sl
  #pragma unroll
  for (int mf = 0; mf < 4; mf++) {
    const int r0 = mt * 128 + mw + mf * 16 + g;
    const int f0  = r0 >> 11;
    const int bb0 = (r0 >> 10) & 1;
    const int sl0 = r0 & 1023;
    float* ob0 = out + (size_t)bb0 * 8388608 + f0 * 1024 + sl0;
    float* ob1 = ob0 + 8;              // r0+8 stays in same f/bb block
    #pragma unroll
    for (int nf = 0; nf < 8; nf++) {
      const int c0 = n0 + nw + nf * 8 + t * 2;
      ob0[(size_t)(c0    ) * 16384] = acc[mf][nf][0];
      ob0[(size_t)(c0 + 1) * 16384] = acc[mf][nf][1];
      ob1[(size_t)(c0    ) * 16384] = acc[mf][nf][2];
      ob1[(size_t)(c0 + 1) * 16384] = acc[mf][nf][3];
    }
  }
}

// ---------------------------------------------------------------------------
extern "C" void kernel_launch(void* const* d_in, const int* in_sizes, int n_in,
                              void* d_out, int out_size)
{
  (void)in_sizes; (void)n_in; (void)out_size;
  const float* x  = (const float*)d_in[0];
  const float* pb = (const float*)d_in[1];
  const float* wq = (const float*)d_in[2];
  const float* wo = (const float*)d_in[3];
  float* out = (float*)d_out;

  cudaFuncSetAttribute(gemm_qkv_kernel, cudaFuncAttributeMaxDynamicSharedMemorySize, G1_SMEM);
  cudaFuncSetAttribute(gemm_out_kernel, cudaFuncAttributeMaxDynamicSharedMemorySize, G3_SMEM);

  uint32_t* wqh; cudaGetSymbolAddress((void**)&wqh, g_wqh);
  uint32_t* woh; cudaGetSymbolAddress((void**)&woh, g_woh);

  dim3 gp(256, 32);  pack_x_kernel<<<gp, 256>>>(x);
  pack_w_kernel<<<1536, 256>>>(wq, wqh, 1536);
  pack_w_kernel<<<512, 256>>>(wo, woh, 512);

  dim3 g1(6, 256);   gemm_qkv_kernel<<<g1, 256, G1_SMEM>>>();
  dim3 ga(2048, 8);  attn_kernel<<<ga, 128>>>(pb);
  dim3 g3(2, 256);   gemm_out_kernel<<<g3, 256, G3_SMEM>>>(out);
}